// round 6
// baseline (speedup 1.0000x reference)
#include <cuda_runtime.h>
#include <cuda_bf16.h>
#include <math.h>
#include <stdint.h>

#define NN   65536
#define KX   512
#define AA   64
#define DD   8
#define PP   96
#define NB2  (NN/128)
#define MOMW (AA + AA*AA)

// ---------------- scratch ----------------
__device__ __align__(16) float g_t  [(size_t)NN*AA];
__device__ __align__(16) float g_rep[(size_t)NN*AA];
__device__ __align__(16) float g_part[(size_t)NB2*MOMW];
__device__ __align__(16) float g_m[AA];
__device__ __align__(16) float g_S[AA*AA];
__device__ __align__(16) float g_scale[DD*AA];
__device__ __align__(16) float g_shift[DD*AA];

__device__ __forceinline__ float eluf(float v) { return v > 0.f ? v : expm1f(v); }

// split-pack: two floats -> bf16x2 hi word (returned) and lo word (*lo)
__device__ __forceinline__ uint32_t pack2(float f0, float f1, uint32_t* lo) {
    __nv_bfloat16 h0 = __float2bfloat16(f0);
    __nv_bfloat16 h1 = __float2bfloat16(f1);
    __nv_bfloat16 l0 = __float2bfloat16(f0 - __bfloat162float(h0));
    __nv_bfloat16 l1 = __float2bfloat16(f1 - __bfloat162float(h1));
    *lo = (uint32_t)__bfloat16_as_ushort(l0) | ((uint32_t)__bfloat16_as_ushort(l1) << 16);
    return (uint32_t)__bfloat16_as_ushort(h0) | ((uint32_t)__bfloat16_as_ushort(h1) << 16);
}
__device__ __forceinline__ void mma_bf16(float* c, const uint32_t* a, const uint32_t* b) {
    asm volatile("mma.sync.aligned.m16n8k16.row.col.f32.bf16.bf16.f32 "
                 "{%0,%1,%2,%3}, {%4,%5,%6,%7}, {%8,%9}, {%0,%1,%2,%3};"
                 : "+f"(c[0]), "+f"(c[1]), "+f"(c[2]), "+f"(c[3])
                 : "r"(a[0]), "r"(a[1]), "r"(a[2]), "r"(a[3]), "r"(b[0]), "r"(b[1]));
}
// A-fragment word index for m16n8k16 over a 128x64 tile; (row, col2) with col2 even.
__device__ __forceinline__ int afragw(int row, int col2) {
    int m32 = row >> 5, mt = (row >> 4) & 1, ks = col2 >> 4;
    int rI = row & 15, cI = col2 & 15;
    int ln = (rI & 7) * 4 + ((cI >> 1) & 3);
    int j  = ((cI >> 3) << 1) | (rI >> 3);
    return (((m32 * 4 + ks) * 32 + ln) * 2 + mt) * 4 + j;
}

// ---------------- K1: t = normalize_rows(x @ shuzhihua) (fp32 exact) ----------------
__global__ __launch_bounds__(256) void k1_gemm_norm(const float* __restrict__ x,
                                                    const float* __restrict__ B) {
    __shared__ __align__(16) float As[128 * 64];
    __shared__ __align__(16) float Bs[64 * 64];
    int row0 = blockIdx.x * 128;
    int tid = threadIdx.x;
    int tc = tid & 15, tr = tid >> 4;
    int r0 = tr * 8, c0 = tc * 4;
    float acc[8][4] = {};
    for (int k0 = 0; k0 < KX; k0 += 64) {
        for (int l = tid; l < 2048; l += 256) {
            int kk4 = (l & 15) * 4, r = l >> 4;
            *(float4*)&As[r * 64 + kk4] =
                *(const float4*)&x[(size_t)(row0 + r) * KX + k0 + kk4];
        }
        for (int l = tid; l < 1024; l += 256) {
            int c4 = (l & 15) * 4, kk = l >> 4;
            *(float4*)&Bs[kk * 64 + c4] =
                *(const float4*)&B[(size_t)(k0 + kk) * AA + c4];
        }
        __syncthreads();
#pragma unroll 8
        for (int kk = 0; kk < 64; ++kk) {
            float4 bv = *(const float4*)&Bs[kk * 64 + c0];
            float av[8];
#pragma unroll
            for (int i = 0; i < 8; i++) av[i] = As[(r0 + i) * 64 + kk];
#pragma unroll
            for (int i = 0; i < 8; i++) {
                acc[i][0] = fmaf(av[i], bv.x, acc[i][0]);
                acc[i][1] = fmaf(av[i], bv.y, acc[i][1]);
                acc[i][2] = fmaf(av[i], bv.z, acc[i][2]);
                acc[i][3] = fmaf(av[i], bv.w, acc[i][3]);
            }
        }
        __syncthreads();
    }
    float* red = Bs;
    float* rs  = Bs + 128 * 17;
#pragma unroll
    for (int i = 0; i < 8; i++) {
        float ss = acc[i][0]*acc[i][0] + acc[i][1]*acc[i][1]
                 + acc[i][2]*acc[i][2] + acc[i][3]*acc[i][3];
        red[(r0 + i) * 17 + tc] = ss;
    }
    __syncthreads();
    if (tid < 128) {
        float s = 0.f;
#pragma unroll
        for (int q = 0; q < 16; q++) s += red[tid * 17 + q];
        rs[tid] = 1.0f / fmaxf(sqrtf(s), 1e-12f);
    }
    __syncthreads();
#pragma unroll
    for (int i = 0; i < 8; i++) {
        float sc = rs[r0 + i];
        float4 v = make_float4(acc[i][0]*sc, acc[i][1]*sc, acc[i][2]*sc, acc[i][3]*sc);
        *(float4*)&g_t[(size_t)(row0 + r0 + i) * AA + c0] = v;
    }
}

// ---------------- K2: rep window-sum + per-block moments (fp32 exact) ----------------
__global__ __launch_bounds__(256) void k2_rep(const float* __restrict__ lw,
                                              const float* __restrict__ lb,
                                              float* __restrict__ orep) {
    __shared__ float ts[143 * 64];
    __shared__ float ws[16 * 64];
    __shared__ float bsum[64];
    __shared__ float mred[4][64];
    int row0 = blockIdx.x * 128;
    int base = row0 - 15;
    int tid = threadIdx.x;
    for (int l = tid; l < 143 * 64; l += 256) {
        int r = l >> 6, a = l & 63;
        int g = base + r; if (g < 0) g = 0;
        ts[l] = g_t[(size_t)g * 64 + a];
    }
    for (int l = tid; l < 1024; l += 256) ws[l] = lw[l];
    if (tid < 64) {
        float s = 0.f;
        for (int j = 0; j < 16; j++) s += lb[j * 64 + tid];
        bsum[tid] = s;
    }
    __syncthreads();
    int a = tid & 63, rg = tid >> 6;
    float ms = 0.f;
    for (int i = 0; i < 32; i++) {
        int r = rg * 32 + i;
        int n = row0 + r;
        float acc = bsum[a];
        if (n >= 15) {
#pragma unroll
            for (int j = 0; j < 16; j++) acc += ws[j * 64 + a] * ts[(r + j) * 64 + a];
        } else {
            for (int j = 0; j < 16; j++) {
                int lj = min(j, n) + 15;
                acc += ws[j * 64 + a] * ts[lj * 64 + a];
            }
        }
        g_rep[(size_t)n * 64 + a] = acc;
        if (orep) orep[(size_t)n * 64 + a] = acc;
        ms += acc;
    }
    mred[rg][a] = ms;
    __syncthreads();
    if (tid < 64)
        g_part[(size_t)blockIdx.x * MOMW + tid] =
            mred[0][tid] + mred[1][tid] + mred[2][tid] + mred[3][tid];
    int bi = tid & 15, ai = tid >> 4;
    int a4 = ai * 4, b4 = bi * 4;
    float sa[4][4] = {};
    const float* rp = &g_rep[(size_t)row0 * 64];
    for (int r = 0; r < 128; r++) {
        float4 av = *(const float4*)&rp[r * 64 + a4];
        float4 bv = *(const float4*)&rp[r * 64 + b4];
        float am[4] = {av.x, av.y, av.z, av.w};
        float bm[4] = {bv.x, bv.y, bv.z, bv.w};
#pragma unroll
        for (int i = 0; i < 4; i++)
#pragma unroll
            for (int j = 0; j < 4; j++) sa[i][j] = fmaf(am[i], bm[j], sa[i][j]);
    }
    float* sp = &g_part[(size_t)blockIdx.x * MOMW + 64];
#pragma unroll
    for (int i = 0; i < 4; i++)
        *(float4*)&sp[(a4 + i) * 64 + b4] = make_float4(sa[i][0], sa[i][1], sa[i][2], sa[i][3]);
}

// ---------------- K2b: deterministic partial reduce ----------------
__global__ void k2b_reduce() {
    int e = blockIdx.x * 128 + threadIdx.x;
    if (e >= MOMW) return;
    float s0 = 0.f, s1 = 0.f, s2 = 0.f, s3 = 0.f;
    for (int k = 0; k < NB2; k += 4) {
        s0 += g_part[(size_t)(k    ) * MOMW + e];
        s1 += g_part[(size_t)(k + 1) * MOMW + e];
        s2 += g_part[(size_t)(k + 2) * MOMW + e];
        s3 += g_part[(size_t)(k + 3) * MOMW + e];
    }
    float s = (s0 + s1) + (s2 + s3);
    if (e < 64) g_m[e] = s; else g_S[e - 64] = s;
}

// ---------------- K3: BN scale/shift via q = w^T S w ----------------
__global__ __launch_bounds__(512) void k3m(const float* __restrict__ W1,
                                           const float* __restrict__ gamma,
                                           const float* __restrict__ beta) {
    __shared__ float Ss[4096];
    __shared__ float Ws1[64 * 65];
    __shared__ float ms[64];
    __shared__ float qred[8][64], mured[8][64];
    int d = blockIdx.x, tid = threadIdx.x;
    for (int l = tid; l < 4096; l += 512) {
        Ss[l] = g_S[l];
        Ws1[(l >> 6) * 65 + (l & 63)] = W1[(size_t)d * 4096 + l];
    }
    if (tid < 64) ms[tid] = g_m[tid];
    __syncthreads();
    int b = tid & 63, iq = tid >> 6;
    float q = 0.f, mu = 0.f;
    for (int i = iq * 8; i < iq * 8 + 8; i++) {
        float wi = Ws1[i * 65 + b];
        mu = fmaf(ms[i], wi, mu);
        float tmp = 0.f;
#pragma unroll 8
        for (int j = 0; j < 64; j++) tmp = fmaf(Ss[i * 64 + j], Ws1[j * 65 + b], tmp);
        q = fmaf(wi, tmp, q);
    }
    qred[iq][b] = q; mured[iq][b] = mu;
    __syncthreads();
    if (tid < 64) {
        float Q = 0.f, MU = 0.f;
#pragma unroll
        for (int r = 0; r < 8; r++) { Q += qred[r][tid]; MU += mured[r][tid]; }
        const float invN = 1.0f / (float)NN;
        float mean = MU * invN;
        float var = Q * invN - mean * mean;
        float s = gamma[d * 64 + tid] * rsqrtf(var + 1e-5f);
        g_scale[d * 64 + tid] = s;
        g_shift[d * 64 + tid] = beta[d * 64 + tid] - mean * s;
    }
}

// ---------------- K4m: fused towers on mma.sync bf16x2 (hi/lo split) ----------------
// word offsets: AfH 0 | AfL 4096 | HfH 8192 | HfL 12288 | B1H 16384 | B1L 18432
//               B2H 20480 | B2L 23552 | scl 26624 | shf 26688 | b2s 26752..26848
#define K4M_WORDS 26848
#define K4M_SMEM  (K4M_WORDS * 4)
__global__ __launch_bounds__(256, 2) void k4m(const float* __restrict__ W1,
                                              const float* __restrict__ W2,
                                              const float* __restrict__ b2,
                                              float* __restrict__ out) {
    extern __shared__ __align__(16) uint32_t sw[];
    uint32_t* AfH = sw;
    uint32_t* AfL = sw + 4096;
    uint32_t* HfH = sw + 8192;
    uint32_t* HfL = sw + 12288;
    uint32_t* B1H = sw + 16384;
    uint32_t* B1L = sw + 18432;
    uint32_t* B2H = sw + 20480;
    uint32_t* B2L = sw + 23552;
    float* scl = (float*)(sw + 26624);
    float* shf = (float*)(sw + 26688);
    float* b2s = (float*)(sw + 26752);
    int tid = threadIdx.x;
    int lane = tid & 31, warp = tid >> 5;
    int wm = warp & 3, wn = warp >> 2;     // 4 M-warps (32 rows each) x 2 N-warps
    int row0 = blockIdx.x * 128;

    // stage A = rep tile -> bf16 hi/lo fragments (once, reused for all 8 towers)
    for (int l = tid; l < 4096; l += 256) {
        int row = l >> 5, col2 = (l & 31) * 2;
        const float* rp = &g_rep[(size_t)(row0 + row) * 64 + col2];
        uint32_t lo, hi = pack2(rp[0], rp[1], &lo);
        int w = afragw(row, col2);
        AfH[w] = hi; AfL[w] = lo;
    }

    for (int d = 0; d < 8; d++) {
        __syncthreads();   // prev iter done reading B1/B2/Hf (and Af staged, d=0)
        const float* w1p = W1 + (size_t)d * 4096;
        for (int l = tid; l < 2048; l += 256) {
            int n = l >> 5, k2 = (l & 31) * 2;
            uint32_t lo, hi = pack2(w1p[k2 * 64 + n], w1p[(k2 + 1) * 64 + n], &lo);
            int wn_ = n >> 5, nt = (n >> 3) & 3, nn = n & 7;
            int ks = k2 >> 4, kI = k2 & 15;
            int ln = nn * 4 + ((kI >> 1) & 3), j = kI >> 3;
            int w = (((wn_ * 4 + ks) * 4 + nt) * 32 + ln) * 2 + j;
            B1H[w] = hi; B1L[w] = lo;
        }
        const float* w2p = W2 + (size_t)d * 6144;
        for (int l = tid; l < 3072; l += 256) {
            int n = l >> 5, k2 = (l & 31) * 2;
            uint32_t lo, hi = pack2(w2p[k2 * 96 + n], w2p[(k2 + 1) * 96 + n], &lo);
            int wn2 = n / 48, nt = (n - wn2 * 48) >> 3, nn = n & 7;
            int ks = k2 >> 4, kI = k2 & 15;
            int ln = nn * 4 + ((kI >> 1) & 3), j = kI >> 3;
            int w = (((wn2 * 4 + ks) * 6 + nt) * 32 + ln) * 2 + j;
            B2H[w] = hi; B2L[w] = lo;
        }
        if (tid < 64) { scl[tid] = g_scale[d * 64 + tid]; shf[tid] = g_shift[d * 64 + tid]; }
        if (tid < 96) b2s[tid] = b2[d * 96 + tid];
        __syncthreads();

        // ---- GEMM1: H = rep @ W1[d]  (hi*hi + hi*lo + lo*hi) ----
        float c1[2][4][4] = {};
#pragma unroll
        for (int ks = 0; ks < 4; ks++) {
            uint32_t ah[2][4], al[2][4];
#pragma unroll
            for (int mt = 0; mt < 2; mt++) {
                int base = (((wm * 4 + ks) * 32 + lane) * 2 + mt) * 4;
                *(uint4*)ah[mt] = *(const uint4*)&AfH[base];
                *(uint4*)al[mt] = *(const uint4*)&AfL[base];
            }
            uint32_t bh[4][2], bl[4][2];
#pragma unroll
            for (int nt = 0; nt < 4; nt++) {
                int base = (((wn * 4 + ks) * 4 + nt) * 32 + lane) * 2;
                *(uint2*)bh[nt] = *(const uint2*)&B1H[base];
                *(uint2*)bl[nt] = *(const uint2*)&B1L[base];
            }
#pragma unroll
            for (int mt = 0; mt < 2; mt++)
#pragma unroll
                for (int nt = 0; nt < 4; nt++) {
                    mma_bf16(c1[mt][nt], ah[mt], bh[nt]);
                    mma_bf16(c1[mt][nt], ah[mt], bl[nt]);
                    mma_bf16(c1[mt][nt], al[mt], bh[nt]);
                }
        }
        // ---- BN + ELU -> Hf (hi/lo fragment layout) ----
#pragma unroll
        for (int mt = 0; mt < 2; mt++)
#pragma unroll
            for (int nt = 0; nt < 4; nt++) {
                int colb = wn * 32 + nt * 8 + (lane & 3) * 2;
                float s0 = scl[colb], s1 = scl[colb + 1];
                float f0 = shf[colb], f1 = shf[colb + 1];
#pragma unroll
                for (int jp = 0; jp < 2; jp++) {
                    int row = wm * 32 + mt * 16 + (lane >> 2) + jp * 8;
                    float v0 = eluf(fmaf(c1[mt][nt][jp * 2 + 0], s0, f0));
                    float v1 = eluf(fmaf(c1[mt][nt][jp * 2 + 1], s1, f1));
                    uint32_t lo, hi = pack2(v0, v1, &lo);
                    int w = afragw(row, colb);
                    HfH[w] = hi; HfL[w] = lo;
                }
            }
        __syncthreads();

        // ---- GEMM2: Y = H @ W2[d] + b2 ----
        float c2[2][6][4] = {};
#pragma unroll
        for (int ks = 0; ks < 4; ks++) {
            uint32_t ah[2][4], al[2][4];
#pragma unroll
            for (int mt = 0; mt < 2; mt++) {
                int base = (((wm * 4 + ks) * 32 + lane) * 2 + mt) * 4;
                *(uint4*)ah[mt] = *(const uint4*)&HfH[base];
                *(uint4*)al[mt] = *(const uint4*)&HfL[base];
            }
            uint32_t bh[6][2], bl[6][2];
#pragma unroll
            for (int nt = 0; nt < 6; nt++) {
                int base = (((wn * 4 + ks) * 6 + nt) * 32 + lane) * 2;
                *(uint2*)bh[nt] = *(const uint2*)&B2H[base];
                *(uint2*)bl[nt] = *(const uint2*)&B2L[base];
            }
#pragma unroll
            for (int mt = 0; mt < 2; mt++)
#pragma unroll
                for (int nt = 0; nt < 6; nt++) {
                    mma_bf16(c2[mt][nt], ah[mt], bh[nt]);
                    mma_bf16(c2[mt][nt], ah[mt], bl[nt]);
                    mma_bf16(c2[mt][nt], al[mt], bh[nt]);
                }
        }
#pragma unroll
        for (int mt = 0; mt < 2; mt++)
#pragma unroll
            for (int nt = 0; nt < 6; nt++)
#pragma unroll
                for (int j = 0; j < 4; j++) {
                    int row = wm * 32 + mt * 16 + (lane >> 2) + ((j >> 1) << 3);
                    int col = wn * 48 + nt * 8 + ((lane & 3) << 1) + (j & 1);
                    out[(size_t)(row0 + row) * 768 + (size_t)col * 8 + d] =
                        c2[mt][nt][j] + b2s[col];
                }
    }
}

// ---------------- launch ----------------
extern "C" void kernel_launch(void* const* d_in, const int* in_sizes, int n_in,
                              void* d_out, int out_size) {
    const float* x     = (const float*)d_in[0];
    const float* shz   = (const float*)d_in[1];
    const float* lw    = (const float*)d_in[2];
    const float* lb    = (const float*)d_in[3];
    const float* W1    = (const float*)d_in[4];
    // d_in[5] = b1: cancels inside BatchNorm, unused
    const float* gamma = (const float*)d_in[6];
    const float* beta  = (const float*)d_in[7];
    const float* W2    = (const float*)d_in[8];
    const float* b2    = (const float*)d_in[9];
    float* out = (float*)d_out;

    float* orep = nullptr;
    if ((long long)out_size >= (long long)NN * 832)
        orep = out + (size_t)NN * 768;

    cudaFuncSetAttribute(k4m, cudaFuncAttributeMaxDynamicSharedMemorySize, K4M_SMEM);

    k1_gemm_norm<<<NN / 128, 256>>>(x, shz);
    k2_rep<<<NN / 128, 256>>>(lw, lb, orep);
    k2b_reduce<<<(MOMW + 127) / 128, 128>>>();
    k3m<<<DD, 512>>>(W1, gamma, beta);
    k4m<<<NN / 128, 256, K4M_SMEM>>>(W1, W2, b2, out);
}

// round 7
// speedup vs baseline: 1.3940x; 1.3940x over previous
#include <cuda_runtime.h>
#include <cuda_bf16.h>
#include <math.h>
#include <stdint.h>

#define NN   65536
#define KX   512
#define AA   64
#define DD   8
#define PP   96
#define NB2  (NN/128)
#define MOMW (AA + AA*AA)

// ---------------- scratch ----------------
__device__ __align__(16) float g_t  [(size_t)NN*AA];
__device__ __align__(16) float g_rep[(size_t)NN*AA];
__device__ __align__(16) float g_part[(size_t)NB2*MOMW];
__device__ __align__(16) float g_m[AA];
__device__ __align__(16) float g_S[AA*AA];
__device__ __align__(16) float g_scale[DD*AA];
__device__ __align__(16) float g_shift[DD*AA];

__device__ __forceinline__ float eluf(float v) { return v > 0.f ? v : expm1f(v); }

// split-pack: two floats -> bf16x2 hi word (returned) and lo word (*lo)
__device__ __forceinline__ uint32_t pack2(float f0, float f1, uint32_t* lo) {
    __nv_bfloat16 h0 = __float2bfloat16(f0);
    __nv_bfloat16 h1 = __float2bfloat16(f1);
    __nv_bfloat16 l0 = __float2bfloat16(f0 - __bfloat162float(h0));
    __nv_bfloat16 l1 = __float2bfloat16(f1 - __bfloat162float(h1));
    *lo = (uint32_t)__bfloat16_as_ushort(l0) | ((uint32_t)__bfloat16_as_ushort(l1) << 16);
    return (uint32_t)__bfloat16_as_ushort(h0) | ((uint32_t)__bfloat16_as_ushort(h1) << 16);
}
__device__ __forceinline__ void mma_bf16(float* c, const uint32_t* a, const uint32_t* b) {
    asm volatile("mma.sync.aligned.m16n8k16.row.col.f32.bf16.bf16.f32 "
                 "{%0,%1,%2,%3}, {%4,%5,%6,%7}, {%8,%9}, {%0,%1,%2,%3};"
                 : "+f"(c[0]), "+f"(c[1]), "+f"(c[2]), "+f"(c[3])
                 : "r"(a[0]), "r"(a[1]), "r"(a[2]), "r"(a[3]), "r"(b[0]), "r"(b[1]));
}
// A-fragment word index for m16n8k16 over a 128x64 tile; (row, col2) with col2 even.
__device__ __forceinline__ int afragw(int row, int col2) {
    int m32 = row >> 5, mt = (row >> 4) & 1, ks = col2 >> 4;
    int rI = row & 15, cI = col2 & 15;
    int ln = (rI & 7) * 4 + ((cI >> 1) & 3);
    int j  = ((cI >> 3) << 1) | (rI >> 3);
    return (((m32 * 4 + ks) * 32 + ln) * 2 + mt) * 4 + j;
}

// ---------------- K1: t = normalize_rows(x @ shuzhihua) (fp32 exact) ----------------
__global__ __launch_bounds__(256) void k1_gemm_norm(const float* __restrict__ x,
                                                    const float* __restrict__ B) {
    __shared__ __align__(16) float As[128 * 64];
    __shared__ __align__(16) float Bs[64 * 64];
    int row0 = blockIdx.x * 128;
    int tid = threadIdx.x;
    int tc = tid & 15, tr = tid >> 4;
    int r0 = tr * 8, c0 = tc * 4;
    float acc[8][4] = {};
    for (int k0 = 0; k0 < KX; k0 += 64) {
        for (int l = tid; l < 2048; l += 256) {
            int kk4 = (l & 15) * 4, r = l >> 4;
            *(float4*)&As[r * 64 + kk4] =
                *(const float4*)&x[(size_t)(row0 + r) * KX + k0 + kk4];
        }
        for (int l = tid; l < 1024; l += 256) {
            int c4 = (l & 15) * 4, kk = l >> 4;
            *(float4*)&Bs[kk * 64 + c4] =
                *(const float4*)&B[(size_t)(k0 + kk) * AA + c4];
        }
        __syncthreads();
#pragma unroll 8
        for (int kk = 0; kk < 64; ++kk) {
            float4 bv = *(const float4*)&Bs[kk * 64 + c0];
            float av[8];
#pragma unroll
            for (int i = 0; i < 8; i++) av[i] = As[(r0 + i) * 64 + kk];
#pragma unroll
            for (int i = 0; i < 8; i++) {
                acc[i][0] = fmaf(av[i], bv.x, acc[i][0]);
                acc[i][1] = fmaf(av[i], bv.y, acc[i][1]);
                acc[i][2] = fmaf(av[i], bv.z, acc[i][2]);
                acc[i][3] = fmaf(av[i], bv.w, acc[i][3]);
            }
        }
        __syncthreads();
    }
    float* red = Bs;
    float* rs  = Bs + 128 * 17;
#pragma unroll
    for (int i = 0; i < 8; i++) {
        float ss = acc[i][0]*acc[i][0] + acc[i][1]*acc[i][1]
                 + acc[i][2]*acc[i][2] + acc[i][3]*acc[i][3];
        red[(r0 + i) * 17 + tc] = ss;
    }
    __syncthreads();
    if (tid < 128) {
        float s = 0.f;
#pragma unroll
        for (int q = 0; q < 16; q++) s += red[tid * 17 + q];
        rs[tid] = 1.0f / fmaxf(sqrtf(s), 1e-12f);
    }
    __syncthreads();
#pragma unroll
    for (int i = 0; i < 8; i++) {
        float sc = rs[r0 + i];
        float4 v = make_float4(acc[i][0]*sc, acc[i][1]*sc, acc[i][2]*sc, acc[i][3]*sc);
        *(float4*)&g_t[(size_t)(row0 + r0 + i) * AA + c0] = v;
    }
}

// ---------------- K2: rep window-sum + per-block moments (fp32 exact) ----------------
__global__ __launch_bounds__(256) void k2_rep(const float* __restrict__ lw,
                                              const float* __restrict__ lb,
                                              float* __restrict__ orep) {
    __shared__ float ts[143 * 64];
    __shared__ float ws[16 * 64];
    __shared__ float bsum[64];
    __shared__ float mred[4][64];
    int row0 = blockIdx.x * 128;
    int base = row0 - 15;
    int tid = threadIdx.x;
    for (int l = tid; l < 143 * 64; l += 256) {
        int r = l >> 6, a = l & 63;
        int g = base + r; if (g < 0) g = 0;
        ts[l] = g_t[(size_t)g * 64 + a];
    }
    for (int l = tid; l < 1024; l += 256) ws[l] = lw[l];
    if (tid < 64) {
        float s = 0.f;
        for (int j = 0; j < 16; j++) s += lb[j * 64 + tid];
        bsum[tid] = s;
    }
    __syncthreads();
    int a = tid & 63, rg = tid >> 6;
    float ms = 0.f;
    for (int i = 0; i < 32; i++) {
        int r = rg * 32 + i;
        int n = row0 + r;
        float acc = bsum[a];
        if (n >= 15) {
#pragma unroll
            for (int j = 0; j < 16; j++) acc += ws[j * 64 + a] * ts[(r + j) * 64 + a];
        } else {
            for (int j = 0; j < 16; j++) {
                int lj = min(j, n) + 15;
                acc += ws[j * 64 + a] * ts[lj * 64 + a];
            }
        }
        g_rep[(size_t)n * 64 + a] = acc;
        if (orep) orep[(size_t)n * 64 + a] = acc;
        ms += acc;
    }
    mred[rg][a] = ms;
    __syncthreads();
    if (tid < 64)
        g_part[(size_t)blockIdx.x * MOMW + tid] =
            mred[0][tid] + mred[1][tid] + mred[2][tid] + mred[3][tid];
    int bi = tid & 15, ai = tid >> 4;
    int a4 = ai * 4, b4 = bi * 4;
    float sa[4][4] = {};
    const float* rp = &g_rep[(size_t)row0 * 64];
    for (int r = 0; r < 128; r++) {
        float4 av = *(const float4*)&rp[r * 64 + a4];
        float4 bv = *(const float4*)&rp[r * 64 + b4];
        float am[4] = {av.x, av.y, av.z, av.w};
        float bm[4] = {bv.x, bv.y, bv.z, bv.w};
#pragma unroll
        for (int i = 0; i < 4; i++)
#pragma unroll
            for (int j = 0; j < 4; j++) sa[i][j] = fmaf(am[i], bm[j], sa[i][j]);
    }
    float* sp = &g_part[(size_t)blockIdx.x * MOMW + 64];
#pragma unroll
    for (int i = 0; i < 4; i++)
        *(float4*)&sp[(a4 + i) * 64 + b4] = make_float4(sa[i][0], sa[i][1], sa[i][2], sa[i][3]);
}

// ---------------- K2b: deterministic partial reduce ----------------
__global__ void k2b_reduce() {
    int e = blockIdx.x * 128 + threadIdx.x;
    if (e >= MOMW) return;
    float s0 = 0.f, s1 = 0.f, s2 = 0.f, s3 = 0.f;
    for (int k = 0; k < NB2; k += 4) {
        s0 += g_part[(size_t)(k    ) * MOMW + e];
        s1 += g_part[(size_t)(k + 1) * MOMW + e];
        s2 += g_part[(size_t)(k + 2) * MOMW + e];
        s3 += g_part[(size_t)(k + 3) * MOMW + e];
    }
    float s = (s0 + s1) + (s2 + s3);
    if (e < 64) g_m[e] = s; else g_S[e - 64] = s;
}

// ---------------- K3: BN scale/shift via q = w^T S w ----------------
__global__ __launch_bounds__(512) void k3m(const float* __restrict__ W1,
                                           const float* __restrict__ gamma,
                                           const float* __restrict__ beta) {
    __shared__ float Ss[4096];
    __shared__ float Ws1[64 * 65];
    __shared__ float ms[64];
    __shared__ float qred[8][64], mured[8][64];
    int d = blockIdx.x, tid = threadIdx.x;
    for (int l = tid; l < 4096; l += 512) {
        Ss[l] = g_S[l];
        Ws1[(l >> 6) * 65 + (l & 63)] = W1[(size_t)d * 4096 + l];
    }
    if (tid < 64) ms[tid] = g_m[tid];
    __syncthreads();
    int b = tid & 63, iq = tid >> 6;
    float q = 0.f, mu = 0.f;
    for (int i = iq * 8; i < iq * 8 + 8; i++) {
        float wi = Ws1[i * 65 + b];
        mu = fmaf(ms[i], wi, mu);
        float tmp = 0.f;
#pragma unroll 8
        for (int j = 0; j < 64; j++) tmp = fmaf(Ss[i * 64 + j], Ws1[j * 65 + b], tmp);
        q = fmaf(wi, tmp, q);
    }
    qred[iq][b] = q; mured[iq][b] = mu;
    __syncthreads();
    if (tid < 64) {
        float Q = 0.f, MU = 0.f;
#pragma unroll
        for (int r = 0; r < 8; r++) { Q += qred[r][tid]; MU += mured[r][tid]; }
        const float invN = 1.0f / (float)NN;
        float mean = MU * invN;
        float var = Q * invN - mean * mean;
        float s = gamma[d * 64 + tid] * rsqrtf(var + 1e-5f);
        g_scale[d * 64 + tid] = s;
        g_shift[d * 64 + tid] = beta[d * 64 + tid] - mean * s;
    }
}

// ---------------- K4m: fused towers, bf16x2 hi/lo mma.sync, 16 warps (4Mx4N) ----------------
// word offsets: AfH 0 | AfL 4096 | HfH 8192 | HfL 12288 | B1H 16384 | B1L 18432
//               B2H 20480 | B2L 23552 | scl 26624 | shf 26688 | b2s 26752..26848
#define K4M_WORDS 26848
#define K4M_SMEM  (K4M_WORDS * 4)
__global__ __launch_bounds__(512, 1) void k4m(const float* __restrict__ W1,
                                              const float* __restrict__ W2,
                                              const float* __restrict__ b2,
                                              float* __restrict__ out) {
    extern __shared__ __align__(16) uint32_t sw[];
    uint32_t* AfH = sw;
    uint32_t* AfL = sw + 4096;
    uint32_t* HfH = sw + 8192;
    uint32_t* HfL = sw + 12288;
    uint32_t* B1H = sw + 16384;
    uint32_t* B1L = sw + 18432;
    uint32_t* B2H = sw + 20480;
    uint32_t* B2L = sw + 23552;
    float* scl = (float*)(sw + 26624);
    float* shf = (float*)(sw + 26688);
    float* b2s = (float*)(sw + 26752);
    int tid = threadIdx.x;
    int lane = tid & 31, warp = tid >> 5;
    int wm = warp & 3, wn = warp >> 2;     // 4 M-warps (32 rows) x 4 N-warps
    int row0 = blockIdx.x * 128;

    // stage A = rep tile -> bf16 hi/lo fragments (once, reused for all 8 towers)
    for (int l = tid; l < 4096; l += 512) {
        int row = l >> 5, col2 = (l & 31) * 2;
        const float* rp = &g_rep[(size_t)(row0 + row) * 64 + col2];
        uint32_t lo, hi = pack2(rp[0], rp[1], &lo);
        int w = afragw(row, col2);
        AfH[w] = hi; AfL[w] = lo;
    }

    for (int d = 0; d < 8; d++) {
        __syncthreads();   // prev iter done reading B1/B2/Hf (and Af staged, d=0)
        // B1[d]: n-tile split over 4 wn groups of 16 cols (2 n8-tiles each)
        const float* w1p = W1 + (size_t)d * 4096;
        for (int l = tid; l < 2048; l += 512) {
            int n = l >> 5, k2 = (l & 31) * 2;
            uint32_t lo, hi = pack2(w1p[k2 * 64 + n], w1p[(k2 + 1) * 64 + n], &lo);
            int wn_ = n >> 4, nt = (n >> 3) & 1, nn = n & 7;
            int ks = k2 >> 4, kI = k2 & 15;
            int ln = nn * 4 + ((kI >> 1) & 3), j = kI >> 3;
            int w = (((wn_ * 4 + ks) * 2 + nt) * 32 + ln) * 2 + j;
            B1H[w] = hi; B1L[w] = lo;
        }
        // B2[d]: n-tile split over 4 wn groups of 24 cols (3 n8-tiles each)
        const float* w2p = W2 + (size_t)d * 6144;
        for (int l = tid; l < 3072; l += 512) {
            int n = l >> 5, k2 = (l & 31) * 2;
            uint32_t lo, hi = pack2(w2p[k2 * 96 + n], w2p[(k2 + 1) * 96 + n], &lo);
            int wn2 = n / 24, nr = n - wn2 * 24;
            int nt = nr >> 3, nn = n & 7;
            int ks = k2 >> 4, kI = k2 & 15;
            int ln = nn * 4 + ((kI >> 1) & 3), j = kI >> 3;
            int w = (((wn2 * 4 + ks) * 3 + nt) * 32 + ln) * 2 + j;
            B2H[w] = hi; B2L[w] = lo;
        }
        if (tid < 64) { scl[tid] = g_scale[d * 64 + tid]; shf[tid] = g_shift[d * 64 + tid]; }
        if (tid >= 128 && tid < 224) b2s[tid - 128] = b2[d * 96 + tid - 128];
        __syncthreads();

        // ---- GEMM1: H = rep @ W1[d]  (hi*hi + hi*lo + lo*hi) ----
        float c1[2][2][4] = {};
#pragma unroll
        for (int ks = 0; ks < 4; ks++) {
            uint32_t ah[2][4], al[2][4];
#pragma unroll
            for (int mt = 0; mt < 2; mt++) {
                int base = (((wm * 4 + ks) * 32 + lane) * 2 + mt) * 4;
                *(uint4*)ah[mt] = *(const uint4*)&AfH[base];
                *(uint4*)al[mt] = *(const uint4*)&AfL[base];
            }
            uint32_t bh[2][2], bl[2][2];
#pragma unroll
            for (int nt = 0; nt < 2; nt++) {
                int base = (((wn * 4 + ks) * 2 + nt) * 32 + lane) * 2;
                *(uint2*)bh[nt] = *(const uint2*)&B1H[base];
                *(uint2*)bl[nt] = *(const uint2*)&B1L[base];
            }
#pragma unroll
            for (int mt = 0; mt < 2; mt++)
#pragma unroll
                for (int nt = 0; nt < 2; nt++) {
                    mma_bf16(c1[mt][nt], ah[mt], bh[nt]);
                    mma_bf16(c1[mt][nt], ah[mt], bl[nt]);
                    mma_bf16(c1[mt][nt], al[mt], bh[nt]);
                }
        }
        // ---- BN + ELU -> Hf (hi/lo fragment layout) ----
#pragma unroll
        for (int mt = 0; mt < 2; mt++)
#pragma unroll
            for (int nt = 0; nt < 2; nt++) {
                int colb = wn * 16 + nt * 8 + (lane & 3) * 2;
                float s0 = scl[colb], s1 = scl[colb + 1];
                float f0 = shf[colb], f1 = shf[colb + 1];
#pragma unroll
                for (int jp = 0; jp < 2; jp++) {
                    int row = wm * 32 + mt * 16 + (lane >> 2) + jp * 8;
                    float v0 = eluf(fmaf(c1[mt][nt][jp * 2 + 0], s0, f0));
                    float v1 = eluf(fmaf(c1[mt][nt][jp * 2 + 1], s1, f1));
                    uint32_t lo, hi = pack2(v0, v1, &lo);
                    int w = afragw(row, colb);
                    HfH[w] = hi; HfL[w] = lo;
                }
            }
        __syncthreads();

        // ---- GEMM2: Y = H @ W2[d] + b2 ----
        float c2[2][3][4] = {};
#pragma unroll
        for (int ks = 0; ks < 4; ks++) {
            uint32_t ah[2][4], al[2][4];
#pragma unroll
            for (int mt = 0; mt < 2; mt++) {
                int base = (((wm * 4 + ks) * 32 + lane) * 2 + mt) * 4;
                *(uint4*)ah[mt] = *(const uint4*)&HfH[base];
                *(uint4*)al[mt] = *(const uint4*)&HfL[base];
            }
            uint32_t bh[3][2], bl[3][2];
#pragma unroll
            for (int nt = 0; nt < 3; nt++) {
                int base = (((wn * 4 + ks) * 3 + nt) * 32 + lane) * 2;
                *(uint2*)bh[nt] = *(const uint2*)&B2H[base];
                *(uint2*)bl[nt] = *(const uint2*)&B2L[base];
            }
#pragma unroll
            for (int mt = 0; mt < 2; mt++)
#pragma unroll
                for (int nt = 0; nt < 3; nt++) {
                    mma_bf16(c2[mt][nt], ah[mt], bh[nt]);
                    mma_bf16(c2[mt][nt], ah[mt], bl[nt]);
                    mma_bf16(c2[mt][nt], al[mt], bh[nt]);
                }
        }
#pragma unroll
        for (int mt = 0; mt < 2; mt++)
#pragma unroll
            for (int nt = 0; nt < 3; nt++)
#pragma unroll
                for (int j = 0; j < 4; j++) {
                    int row = wm * 32 + mt * 16 + (lane >> 2) + ((j >> 1) << 3);
                    int col = wn * 24 + nt * 8 + ((lane & 3) << 1) + (j & 1);
                    out[(size_t)(row0 + row) * 768 + (size_t)col * 8 + d] =
                        c2[mt][nt][j] + b2s[col];
                }
    }
}

// ---------------- launch ----------------
extern "C" void kernel_launch(void* const* d_in, const int* in_sizes, int n_in,
                              void* d_out, int out_size) {
    const float* x     = (const float*)d_in[0];
    const float* shz   = (const float*)d_in[1];
    const float* lw    = (const float*)d_in[2];
    const float* lb    = (const float*)d_in[3];
    const float* W1    = (const float*)d_in[4];
    // d_in[5] = b1: cancels inside BatchNorm, unused
    const float* gamma = (const float*)d_in[6];
    const float* beta  = (const float*)d_in[7];
    const float* W2    = (const float*)d_in[8];
    const float* b2    = (const float*)d_in[9];
    float* out = (float*)d_out;

    float* orep = nullptr;
    if ((long long)out_size >= (long long)NN * 832)
        orep = out + (size_t)NN * 768;

    cudaFuncSetAttribute(k4m, cudaFuncAttributeMaxDynamicSharedMemorySize, K4M_SMEM);

    k1_gemm_norm<<<NN / 128, 256>>>(x, shz);
    k2_rep<<<NN / 128, 256>>>(lw, lb, orep);
    k2b_reduce<<<(MOMW + 127) / 128, 128>>>();
    k3m<<<DD, 512>>>(W1, gamma, beta);
    k4m<<<NN / 128, 512, K4M_SMEM>>>(W1, W2, b2, out);
}